// round 1
// baseline (speedup 1.0000x reference)
#include <cuda_runtime.h>
#include <cstddef>

// Problem constants (fixed by the reference):
//   B_PAIRS=2048 pairs, each pair = 44 ligand nodes + 300 protein nodes (stride 344)
//   Only the ligand segment sums (even segments) feed the MLP.
//   MLP: 128 ->256 relu -> 128 relu -> 64 relu -> 1
#define B_PAIRS 2048
#define LIG     44
#define STRIDE  344
#define F_IN    128
#define N0      256
#define N1      128
#define N2      64
#define RTILE   8          // pairs per block
#define THREADS 256

__global__ void __launch_bounds__(THREADS)
staged_fcnn_fused(const float* __restrict__ features,
                  const float* __restrict__ W0, const float* __restrict__ b0,
                  const float* __restrict__ W1, const float* __restrict__ b1,
                  const float* __restrict__ W2, const float* __restrict__ b2,
                  const float* __restrict__ Wout, const float* __restrict__ bout,
                  float* __restrict__ out)
{
    // Transposed activation tiles: [feature][row] so the GEMM inner loops can
    // read all RTILE row-values for one k with two broadcast LDS.128.
    __shared__ float xsT[F_IN][RTILE];   // 4 KB
    __shared__ float h0T[N0][RTILE];     // 8 KB
    __shared__ float h1T[N1][RTILE];     // 4 KB
    __shared__ float h2T[N2][RTILE];     // 2 KB

    const int tid = threadIdx.x;
    const int p0  = blockIdx.x * RTILE;

    // ---------------- Phase 1: ligand segment sum (46 MB total DRAM) ------
    // thread -> (pair pp = tid&7, float4-column c4 = tid>>3). Per warp this
    // touches 8 pairs x 4 c4 = 16 sectors per row — zero wasted bandwidth.
    {
        const int pp = tid & 7;
        const int c4 = tid >> 3;                 // 0..31 (128 floats = 32 float4)
        const float4* src = reinterpret_cast<const float4*>(features)
                          + (size_t)(p0 + pp) * STRIDE * (F_IN / 4) + c4;
        float4 acc = make_float4(0.f, 0.f, 0.f, 0.f);
#pragma unroll 4
        for (int row = 0; row < LIG; ++row) {
            float4 v = src[(size_t)row * (F_IN / 4)];
            acc.x += v.x; acc.y += v.y; acc.z += v.z; acc.w += v.w;
        }
        const int k0 = c4 * 4;
        xsT[k0 + 0][pp] = acc.x;
        xsT[k0 + 1][pp] = acc.y;
        xsT[k0 + 2][pp] = acc.z;
        xsT[k0 + 3][pp] = acc.w;
    }
    __syncthreads();

    // ---------------- Layer 0: [8,128] @ [128,256] + bias, relu -----------
    // thread = output column j; 8 rows register-blocked.
    {
        const int j = tid;                       // 0..255
        const float bj = b0[j];
        float acc[RTILE];
#pragma unroll
        for (int r = 0; r < RTILE; ++r) acc[r] = bj;
#pragma unroll 8
        for (int k = 0; k < F_IN; ++k) {
            const float  w = W0[k * N0 + j];     // coalesced across threads
            const float4 a = *reinterpret_cast<const float4*>(&xsT[k][0]);
            const float4 b = *reinterpret_cast<const float4*>(&xsT[k][4]);
            acc[0] += a.x * w; acc[1] += a.y * w;
            acc[2] += a.z * w; acc[3] += a.w * w;
            acc[4] += b.x * w; acc[5] += b.y * w;
            acc[6] += b.z * w; acc[7] += b.w * w;
        }
        float4 lo = make_float4(fmaxf(acc[0],0.f), fmaxf(acc[1],0.f),
                                fmaxf(acc[2],0.f), fmaxf(acc[3],0.f));
        float4 hi = make_float4(fmaxf(acc[4],0.f), fmaxf(acc[5],0.f),
                                fmaxf(acc[6],0.f), fmaxf(acc[7],0.f));
        *reinterpret_cast<float4*>(&h0T[j][0]) = lo;
        *reinterpret_cast<float4*>(&h0T[j][4]) = hi;
    }
    __syncthreads();

    // ---------------- Layer 1: [8,256] @ [256,128] + bias, relu -----------
    // thread = (column j = tid&127, row-half rh = tid>>7), 4 rows each.
    {
        const int j  = tid & (N1 - 1);
        const int rh = tid >> 7;                 // 0 or 1
        const float bj = b1[j];
        float acc[4];
#pragma unroll
        for (int r = 0; r < 4; ++r) acc[r] = bj;
#pragma unroll 8
        for (int k = 0; k < N0; ++k) {
            const float  w = W1[k * N1 + j];
            const float4 a = *reinterpret_cast<const float4*>(&h0T[k][rh * 4]);
            acc[0] += a.x * w; acc[1] += a.y * w;
            acc[2] += a.z * w; acc[3] += a.w * w;
        }
        float4 v = make_float4(fmaxf(acc[0],0.f), fmaxf(acc[1],0.f),
                               fmaxf(acc[2],0.f), fmaxf(acc[3],0.f));
        *reinterpret_cast<float4*>(&h1T[j][rh * 4]) = v;
    }
    __syncthreads();

    // ---------------- Layer 2: [8,128] @ [128,64] + bias, relu ------------
    // thread = (column j = tid&63, row-quarter rq = tid>>6), 2 rows each.
    {
        const int j  = tid & (N2 - 1);
        const int rq = tid >> 6;                 // 0..3
        const float bj = b2[j];
        float acc0 = bj, acc1 = bj;
#pragma unroll 8
        for (int k = 0; k < N1; ++k) {
            const float  w = W2[k * N2 + j];
            const float2 a = *reinterpret_cast<const float2*>(&h1T[k][rq * 2]);
            acc0 += a.x * w;
            acc1 += a.y * w;
        }
        float2 v = make_float2(fmaxf(acc0, 0.f), fmaxf(acc1, 0.f));
        *reinterpret_cast<float2*>(&h2T[j][rq * 2]) = v;
    }
    __syncthreads();

    // ---------------- Output layer: [8,64] @ [64,1] + bias ----------------
    // warp w reduces row w.
    {
        const int warp = tid >> 5;
        const int lane = tid & 31;
        const int r = warp;                      // 8 warps == RTILE rows
        float s = h2T[2 * lane][r]     * Wout[2 * lane]
                + h2T[2 * lane + 1][r] * Wout[2 * lane + 1];
#pragma unroll
        for (int o = 16; o > 0; o >>= 1)
            s += __shfl_down_sync(0xffffffffu, s, o);
        if (lane == 0)
            out[p0 + r] = s + bout[0];
    }
}

// d_in order (metadata): [0] batch_num_nodes (int64, constant -> unused),
// [1] features, [2] W0, [3] b0, [4] W1, [5] b1, [6] W2, [7] b2,
// [8] Wout, [9] bout.  Output: float32 [2048].
extern "C" void kernel_launch(void* const* d_in, const int* in_sizes, int n_in,
                              void* d_out, int out_size)
{
    const float* features = (const float*)d_in[1];
    const float* W0   = (const float*)d_in[2];
    const float* b0   = (const float*)d_in[3];
    const float* W1   = (const float*)d_in[4];
    const float* b1   = (const float*)d_in[5];
    const float* W2   = (const float*)d_in[6];
    const float* b2   = (const float*)d_in[7];
    const float* Wout = (const float*)d_in[8];
    const float* bout = (const float*)d_in[9];
    float* out = (float*)d_out;

    staged_fcnn_fused<<<B_PAIRS / RTILE, THREADS>>>(
        features, W0, b0, W1, b1, W2, b2, Wout, bout, out);
}

// round 2
// speedup vs baseline: 1.2988x; 1.2988x over previous
#include <cuda_runtime.h>
#include <cstddef>

// Problem constants (fixed by the reference):
//   B_PAIRS=2048 pairs, each pair = 44 ligand nodes + 300 protein nodes (stride 344)
//   Only the ligand segment sums (even segments) feed the MLP.
//   MLP: 128 ->256 relu -> 128 relu -> 64 relu -> 1
#define B_PAIRS 2048
#define LIG     44
#define STRIDE  344
#define F_IN    128
#define N0      256
#define N1      128
#define N2      64
#define RTILE   8
#define THREADS 256

// 1 MB scratch for the per-pair feature sums (device global: allocation-free).
__device__ float g_xs[B_PAIRS * F_IN];

// ---------------- packed fp32x2 helpers (sm_103a FFMA2) --------------------
#define PACK_F32X2(d, lo, hi) \
    asm("mov.b64 %0, {%1, %2};" : "=l"(d) : "f"(lo), "f"(hi))
#define UNPACK_F32X2(lo, hi, v) \
    asm("mov.b64 {%0, %1}, %2;" : "=f"(lo), "=f"(hi) : "l"(v))
#define FMA_F32X2(d, a, b, c) \
    asm("fma.rn.f32x2 %0, %1, %2, %3;" : "=l"(d) : "l"(a), "l"(b), "l"(c))

typedef unsigned long long u64;

// ============================================================================
// Kernel A: ligand segment sum. One block per pair; 256 threads.
//   thread -> (c4 = tid&31 : which float4 of the 128 features,
//              g  = tid>>5 : row group, rows g, g+8, ..., < 44)
// 46 MB streamed once; grid=2048 -> 8 CTAs/SM -> DRAM-bound.
// ============================================================================
__global__ void __launch_bounds__(THREADS)
seg_sum_kernel(const float* __restrict__ features)
{
    __shared__ float4 part[8][32];
    const int tid  = threadIdx.x;
    const int pair = blockIdx.x;
    const int c4   = tid & 31;
    const int g    = tid >> 5;

    const float4* src = reinterpret_cast<const float4*>(features)
                      + (size_t)pair * STRIDE * (F_IN / 4) + c4;
    float4 acc = make_float4(0.f, 0.f, 0.f, 0.f);
#pragma unroll
    for (int r = g; r < LIG; r += 8) {
        float4 v = __ldcs(src + (size_t)r * (F_IN / 4));
        acc.x += v.x; acc.y += v.y; acc.z += v.z; acc.w += v.w;
    }
    part[g][c4] = acc;
    __syncthreads();

    if (tid < 32) {
        float4 s = part[0][tid];
#pragma unroll
        for (int gg = 1; gg < 8; ++gg) {
            float4 v = part[gg][tid];
            s.x += v.x; s.y += v.y; s.z += v.z; s.w += v.w;
        }
        reinterpret_cast<float4*>(g_xs)[pair * (F_IN / 4) + tid] = s;
    }
}

// ============================================================================
// Kernel B: fused 4-layer MLP on 8 rows per block, packed f32x2 math.
// Transposed SMEM tiles [feature][row] -> one LDS.128 yields two f32x2
// operands (row pairs) with no packing; weight broadcast packed once per k.
// ============================================================================
__global__ void __launch_bounds__(THREADS)
mlp_kernel(const float* __restrict__ W0, const float* __restrict__ b0,
           const float* __restrict__ W1, const float* __restrict__ b1,
           const float* __restrict__ W2, const float* __restrict__ b2,
           const float* __restrict__ Wout, const float* __restrict__ bout,
           float* __restrict__ out)
{
    __shared__ float xsT[F_IN][RTILE];   // 4 KB
    __shared__ float h0T[N0][RTILE];     // 8 KB
    __shared__ float h1T[N1][RTILE];     // 4 KB
    __shared__ float h2T[N2][RTILE];     // 2 KB

    const int tid = threadIdx.x;
    const int p0  = blockIdx.x * RTILE;

    // Load this block's 8 summed feature rows into transposed SMEM.
    {
        const int pp = tid & 7;
        const int c4 = tid >> 3;
        float4 v = reinterpret_cast<const float4*>(g_xs)
                       [(size_t)(p0 + pp) * (F_IN / 4) + c4];
        xsT[c4 * 4 + 0][pp] = v.x;
        xsT[c4 * 4 + 1][pp] = v.y;
        xsT[c4 * 4 + 2][pp] = v.z;
        xsT[c4 * 4 + 3][pp] = v.w;
    }
    __syncthreads();

    // ------------- Layer 0: [8,128] @ [128,256] + b, relu ------------------
    {
        const int j = tid;
        const float bj = b0[j];
        u64 acc0, acc1, acc2, acc3;
        PACK_F32X2(acc0, bj, bj); acc1 = acc0; acc2 = acc0; acc3 = acc0;
#pragma unroll 8
        for (int k = 0; k < F_IN; ++k) {
            const float w = W0[k * N0 + j];
            u64 w2; PACK_F32X2(w2, w, w);
            ulonglong2 a = *reinterpret_cast<const ulonglong2*>(&xsT[k][0]);
            ulonglong2 b = *reinterpret_cast<const ulonglong2*>(&xsT[k][4]);
            FMA_F32X2(acc0, a.x, w2, acc0);
            FMA_F32X2(acc1, a.y, w2, acc1);
            FMA_F32X2(acc2, b.x, w2, acc2);
            FMA_F32X2(acc3, b.y, w2, acc3);
        }
        float v0, v1, v2, v3, v4, v5, v6, v7;
        UNPACK_F32X2(v0, v1, acc0); UNPACK_F32X2(v2, v3, acc1);
        UNPACK_F32X2(v4, v5, acc2); UNPACK_F32X2(v6, v7, acc3);
        float4 lo = make_float4(fmaxf(v0,0.f), fmaxf(v1,0.f),
                                fmaxf(v2,0.f), fmaxf(v3,0.f));
        float4 hi = make_float4(fmaxf(v4,0.f), fmaxf(v5,0.f),
                                fmaxf(v6,0.f), fmaxf(v7,0.f));
        *reinterpret_cast<float4*>(&h0T[j][0]) = lo;
        *reinterpret_cast<float4*>(&h0T[j][4]) = hi;
    }
    __syncthreads();

    // ------------- Layer 1: [8,256] @ [256,128] + b, relu ------------------
    {
        const int j  = tid & (N1 - 1);
        const int rh = tid >> 7;                 // 0/1 -> rows rh*4..rh*4+3
        const float bj = b1[j];
        u64 acc0, acc1;
        PACK_F32X2(acc0, bj, bj); acc1 = acc0;
#pragma unroll 8
        for (int k = 0; k < N0; ++k) {
            const float w = W1[k * N1 + j];
            u64 w2; PACK_F32X2(w2, w, w);
            ulonglong2 a = *reinterpret_cast<const ulonglong2*>(&h0T[k][rh * 4]);
            FMA_F32X2(acc0, a.x, w2, acc0);
            FMA_F32X2(acc1, a.y, w2, acc1);
        }
        float v0, v1, v2, v3;
        UNPACK_F32X2(v0, v1, acc0); UNPACK_F32X2(v2, v3, acc1);
        float4 v = make_float4(fmaxf(v0,0.f), fmaxf(v1,0.f),
                               fmaxf(v2,0.f), fmaxf(v3,0.f));
        *reinterpret_cast<float4*>(&h1T[j][rh * 4]) = v;
    }
    __syncthreads();

    // ------------- Layer 2: [8,128] @ [128,64] + b, relu -------------------
    {
        const int j  = tid & (N2 - 1);
        const int rq = tid >> 6;                 // 0..3 -> rows rq*2, rq*2+1
        const float bj = b2[j];
        u64 acc0; PACK_F32X2(acc0, bj, bj);
#pragma unroll 8
        for (int k = 0; k < N1; ++k) {
            const float w = W2[k * N2 + j];
            u64 w2; PACK_F32X2(w2, w, w);
            u64 a = *reinterpret_cast<const u64*>(&h1T[k][rq * 2]);
            FMA_F32X2(acc0, a, w2, acc0);
        }
        float v0, v1; UNPACK_F32X2(v0, v1, acc0);
        float2 v = make_float2(fmaxf(v0, 0.f), fmaxf(v1, 0.f));
        *reinterpret_cast<float2*>(&h2T[j][rq * 2]) = v;
    }
    __syncthreads();

    // ------------- Output: [8,64] @ [64,1] + b -----------------------------
    {
        const int warp = tid >> 5;
        const int lane = tid & 31;
        float s = h2T[2 * lane][warp]     * Wout[2 * lane]
                + h2T[2 * lane + 1][warp] * Wout[2 * lane + 1];
#pragma unroll
        for (int o = 16; o > 0; o >>= 1)
            s += __shfl_down_sync(0xffffffffu, s, o);
        if (lane == 0)
            out[p0 + warp] = s + bout[0];
    }
}

// d_in order (metadata): [0] batch_num_nodes (unused), [1] features,
// [2] W0, [3] b0, [4] W1, [5] b1, [6] W2, [7] b2, [8] Wout, [9] bout.
extern "C" void kernel_launch(void* const* d_in, const int* in_sizes, int n_in,
                              void* d_out, int out_size)
{
    const float* features = (const float*)d_in[1];
    const float* W0   = (const float*)d_in[2];
    const float* b0   = (const float*)d_in[3];
    const float* W1   = (const float*)d_in[4];
    const float* b1   = (const float*)d_in[5];
    const float* W2   = (const float*)d_in[6];
    const float* b2   = (const float*)d_in[7];
    const float* Wout = (const float*)d_in[8];
    const float* bout = (const float*)d_in[9];
    float* out = (float*)d_out;

    seg_sum_kernel<<<B_PAIRS, THREADS>>>(features);
    mlp_kernel<<<B_PAIRS / RTILE, THREADS>>>(W0, b0, W1, b1, W2, b2,
                                             Wout, bout, out);
}

// round 3
// speedup vs baseline: 1.3939x; 1.0732x over previous
#include <cuda_runtime.h>
#include <cstddef>

// Problem constants (fixed by the reference):
//   B_PAIRS=2048 pairs, each pair = 44 ligand nodes + 300 protein nodes (stride 344)
//   Only the ligand segment sums (even segments) feed the MLP.
//   MLP: 128 ->256 relu -> 128 relu -> 64 relu -> 1
#define B_PAIRS 2048
#define LIG     44
#define STRIDE  344
#define F_IN    128
#define N0      256
#define N1      128
#define N2      64
#define RTILE   4          // pairs per MLP block -> grid 512
#define THREADS 256

// 1 MB scratch for the per-pair feature sums (device global: allocation-free).
__device__ float g_xs[B_PAIRS * F_IN];

// ---------------- packed fp32x2 helpers (sm_103a FFMA2) --------------------
#define PACK_F32X2(d, lo, hi) \
    asm("mov.b64 %0, {%1, %2};" : "=l"(d) : "f"(lo), "f"(hi))
#define UNPACK_F32X2(lo, hi, v) \
    asm("mov.b64 {%0, %1}, %2;" : "=f"(lo), "=f"(hi) : "l"(v))
#define FMA_F32X2(d, a, b, c) \
    asm("fma.rn.f32x2 %0, %1, %2, %3;" : "=l"(d) : "l"(a), "l"(b), "l"(c))
#define ADD_F32X2(d, a, b) \
    asm("add.rn.f32x2 %0, %1, %2;" : "=l"(d) : "l"(a), "l"(b))

typedef unsigned long long u64;

// ============================================================================
// Kernel A: ligand segment sum. One block per pair; 256 threads.
// 46 MB streamed once; grid=2048 -> DRAM-bound.
// ============================================================================
__global__ void __launch_bounds__(THREADS)
seg_sum_kernel(const float* __restrict__ features)
{
    __shared__ float4 part[8][32];
    const int tid  = threadIdx.x;
    const int pair = blockIdx.x;
    const int c4   = tid & 31;
    const int g    = tid >> 5;

    const float4* src = reinterpret_cast<const float4*>(features)
                      + (size_t)pair * STRIDE * (F_IN / 4) + c4;
    float4 acc = make_float4(0.f, 0.f, 0.f, 0.f);
#pragma unroll
    for (int r = g; r < LIG; r += 8) {
        float4 v = __ldcs(src + (size_t)r * (F_IN / 4));
        acc.x += v.x; acc.y += v.y; acc.z += v.z; acc.w += v.w;
    }
    part[g][c4] = acc;
    __syncthreads();

    if (tid < 32) {
        float4 s = part[0][tid];
#pragma unroll
        for (int gg = 1; gg < 8; ++gg) {
            float4 v = part[gg][tid];
            s.x += v.x; s.y += v.y; s.z += v.z; s.w += v.w;
        }
        reinterpret_cast<float4*>(g_xs)[pair * (F_IN / 4) + tid] = s;
    }
}

// ============================================================================
// Kernel B: fused 4-layer MLP, 4 rows per block (grid=512), packed f32x2.
// All layers keep 256 threads busy: L0 = 256 cols; L1 = 128 cols x 2 k-halves;
// L2 = 64 cols x 4 k-quarters; partial sums reduced in SMEM via add.rn.f32x2.
// ============================================================================
__global__ void __launch_bounds__(THREADS)
mlp_kernel(const float* __restrict__ W0, const float* __restrict__ b0,
           const float* __restrict__ W1, const float* __restrict__ b1,
           const float* __restrict__ W2, const float* __restrict__ b2,
           const float* __restrict__ Wout, const float* __restrict__ bout,
           float* __restrict__ out)
{
    __shared__ __align__(16) float xsT[F_IN][RTILE];   // 2 KB
    __shared__ __align__(16) float h0T[N0][RTILE];     // 4 KB
    __shared__ __align__(16) float h1T[N1][RTILE];     // 2 KB
    __shared__ __align__(16) float h2T[N2][RTILE];     // 1 KB
    __shared__ __align__(16) float p1[N1][RTILE];      // 2 KB  (L1 kh=1 partial)
    __shared__ __align__(16) float p2[3][N2][RTILE];   // 3 KB  (L2 kq=1..3 partials)

    const int tid = threadIdx.x;
    const int p0  = blockIdx.x * RTILE;

    // Load this block's 4 summed feature rows into transposed SMEM.
    if (tid < 128) {
        const int pp = tid & 3;
        const int c4 = tid >> 2;                 // 0..31
        float4 v = reinterpret_cast<const float4*>(g_xs)
                       [(size_t)(p0 + pp) * (F_IN / 4) + c4];
        xsT[c4 * 4 + 0][pp] = v.x;
        xsT[c4 * 4 + 1][pp] = v.y;
        xsT[c4 * 4 + 2][pp] = v.z;
        xsT[c4 * 4 + 3][pp] = v.w;
    }
    __syncthreads();

    // ------------- Layer 0: [4,128] @ [128,256] + b, relu ------------------
    {
        const int j = tid;                       // 0..255
        const float bj = b0[j];
        u64 acc0, acc1;
        PACK_F32X2(acc0, bj, bj); acc1 = acc0;
#pragma unroll 8
        for (int k = 0; k < F_IN; ++k) {
            const float w = W0[k * N0 + j];
            u64 w2; PACK_F32X2(w2, w, w);
            ulonglong2 a = *reinterpret_cast<const ulonglong2*>(&xsT[k][0]);
            FMA_F32X2(acc0, a.x, w2, acc0);
            FMA_F32X2(acc1, a.y, w2, acc1);
        }
        float v0, v1, v2, v3;
        UNPACK_F32X2(v0, v1, acc0); UNPACK_F32X2(v2, v3, acc1);
        float4 v = make_float4(fmaxf(v0,0.f), fmaxf(v1,0.f),
                               fmaxf(v2,0.f), fmaxf(v3,0.f));
        *reinterpret_cast<float4*>(&h0T[j][0]) = v;
    }
    __syncthreads();

    // ------------- Layer 1: [4,256] @ [256,128] + b, relu (k-split x2) -----
    {
        const int j  = tid & (N1 - 1);           // column
        const int kh = tid >> 7;                 // k-half 0/1
        u64 acc0 = 0ull, acc1 = 0ull;            // (0.f,0.f)
        if (kh == 0) {
            const float bj = b1[j];
            PACK_F32X2(acc0, bj, bj); acc1 = acc0;
        }
        const float* Wp = W1 + (size_t)kh * 128 * N1;
#pragma unroll 8
        for (int kk = 0; kk < 128; ++kk) {
            const float w = Wp[kk * N1 + j];
            u64 w2; PACK_F32X2(w2, w, w);
            ulonglong2 a = *reinterpret_cast<const ulonglong2*>(
                               &h0T[kh * 128 + kk][0]);
            FMA_F32X2(acc0, a.x, w2, acc0);
            FMA_F32X2(acc1, a.y, w2, acc1);
        }
        if (kh == 1) {
            ulonglong2 st; st.x = acc0; st.y = acc1;
            *reinterpret_cast<ulonglong2*>(&p1[j][0]) = st;
        }
        __syncthreads();
        if (kh == 0) {
            ulonglong2 q = *reinterpret_cast<const ulonglong2*>(&p1[j][0]);
            ADD_F32X2(acc0, acc0, q.x);
            ADD_F32X2(acc1, acc1, q.y);
            float v0, v1, v2, v3;
            UNPACK_F32X2(v0, v1, acc0); UNPACK_F32X2(v2, v3, acc1);
            float4 v = make_float4(fmaxf(v0,0.f), fmaxf(v1,0.f),
                                   fmaxf(v2,0.f), fmaxf(v3,0.f));
            *reinterpret_cast<float4*>(&h1T[j][0]) = v;
        }
    }
    __syncthreads();

    // ------------- Layer 2: [4,128] @ [128,64] + b, relu (k-split x4) ------
    {
        const int j  = tid & (N2 - 1);           // column
        const int kq = tid >> 6;                 // k-quarter 0..3
        u64 acc0 = 0ull, acc1 = 0ull;
        if (kq == 0) {
            const float bj = b2[j];
            PACK_F32X2(acc0, bj, bj); acc1 = acc0;
        }
        const int kb = kq * 32;
#pragma unroll 8
        for (int kk = 0; kk < 32; ++kk) {
            const float w = W2[(kb + kk) * N2 + j];
            u64 w2; PACK_F32X2(w2, w, w);
            ulonglong2 a = *reinterpret_cast<const ulonglong2*>(
                               &h1T[kb + kk][0]);
            FMA_F32X2(acc0, a.x, w2, acc0);
            FMA_F32X2(acc1, a.y, w2, acc1);
        }
        if (kq > 0) {
            ulonglong2 st; st.x = acc0; st.y = acc1;
            *reinterpret_cast<ulonglong2*>(&p2[kq - 1][j][0]) = st;
        }
        __syncthreads();
        if (kq == 0) {
#pragma unroll
            for (int t = 0; t < 3; ++t) {
                ulonglong2 q = *reinterpret_cast<const ulonglong2*>(
                                   &p2[t][j][0]);
                ADD_F32X2(acc0, acc0, q.x);
                ADD_F32X2(acc1, acc1, q.y);
            }
            float v0, v1, v2, v3;
            UNPACK_F32X2(v0, v1, acc0); UNPACK_F32X2(v2, v3, acc1);
            float4 v = make_float4(fmaxf(v0,0.f), fmaxf(v1,0.f),
                                   fmaxf(v2,0.f), fmaxf(v3,0.f));
            *reinterpret_cast<float4*>(&h2T[j][0]) = v;
        }
    }
    __syncthreads();

    // ------------- Output: [4,64] @ [64,1] + b -----------------------------
    {
        const int warp = tid >> 5;
        const int lane = tid & 31;
        if (warp < RTILE) {
            float s = h2T[2 * lane][warp]     * Wout[2 * lane]
                    + h2T[2 * lane + 1][warp] * Wout[2 * lane + 1];
#pragma unroll
            for (int o = 16; o > 0; o >>= 1)
                s += __shfl_down_sync(0xffffffffu, s, o);
            if (lane == 0)
                out[p0 + warp] = s + bout[0];
        }
    }
}

// d_in order (metadata): [0] batch_num_nodes (unused), [1] features,
// [2] W0, [3] b0, [4] W1, [5] b1, [6] W2, [7] b2, [8] Wout, [9] bout.
extern "C" void kernel_launch(void* const* d_in, const int* in_sizes, int n_in,
                              void* d_out, int out_size)
{
    const float* features = (const float*)d_in[1];
    const float* W0   = (const float*)d_in[2];
    const float* b0   = (const float*)d_in[3];
    const float* W1   = (const float*)d_in[4];
    const float* b1   = (const float*)d_in[5];
    const float* W2   = (const float*)d_in[6];
    const float* b2   = (const float*)d_in[7];
    const float* Wout = (const float*)d_in[8];
    const float* bout = (const float*)d_in[9];
    float* out = (float*)d_out;

    seg_sum_kernel<<<B_PAIRS, THREADS>>>(features);
    mlp_kernel<<<B_PAIRS / RTILE, THREADS>>>(W0, b0, W1, b1, W2, b2,
                                             Wout, bout, out);
}